// round 1
// baseline (speedup 1.0000x reference)
#include <cuda_runtime.h>
#include <math.h>

#define NU 100000
#define NI 50000
#define NTOT 150000
#define DD 64
#define EE 1250000
#define SS 400000
#define TAU 0.2f
#define EDGE_BIAS 0.5f

// ---- static scratch (no allocations allowed) ----
__device__ float  g_ego[NTOT * DD];      // 38.4 MB
__device__ float  g_xa[NTOT * DD];       // 38.4 MB
__device__ float  g_xb[NTOT * DD];       // 38.4 MB
__device__ float  g_masked[EE];          // 5 MB
__device__ int    g_csr_col[EE];
__device__ float  g_csr_val[EE];
__device__ float  g_csr_mval[EE];
__device__ int    g_counts[NTOT];
__device__ int    g_fillpos[NTOT];
__device__ int    g_rowptr[NTOT + 1];
__device__ int    g_lastS[EE];
__device__ double g_gate_sum;

// ------------------------------------------------------------------
// 1) per-edge init: masked = vals, lastS = 0, counts/fillpos = 0
// ------------------------------------------------------------------
__global__ void k_init_edges(const float* __restrict__ vals) {
    int i = blockIdx.x * blockDim.x + threadIdx.x;
    if (i < EE) { g_masked[i] = vals[i]; g_lastS[i] = 0; }
    if (i < NTOT) { g_counts[i] = 0; g_fillpos[i] = 0; }
    if (i == 0) g_gate_sum = 0.0;
}

// ------------------------------------------------------------------
// 2) build ego = concat(user, item); init both output sum regions to ego
// ------------------------------------------------------------------
__global__ void k_init_ego(const float* __restrict__ user,
                           const float* __restrict__ item,
                           float* __restrict__ out) {
    int i = blockIdx.x * blockDim.x + threadIdx.x;
    if (i >= NTOT * DD) return;
    float v = (i < NU * DD) ? user[i] : item[i - NU * DD];
    g_ego[i] = v;
    out[i] = v;                 // orig-chain sum accumulator
    out[NTOT * DD + i] = v;     // masked-chain sum accumulator
}

// ------------------------------------------------------------------
// 3) last-writer-wins marker for duplicate social_index entries
// ------------------------------------------------------------------
__global__ void k_lastS(const int* __restrict__ sidx) {
    int s = blockIdx.x * blockDim.x + threadIdx.x;
    if (s >= SS) return;
    atomicMax(&g_lastS[sidx[s]], s);
}

// ------------------------------------------------------------------
// 4) gate MLP: warp per social edge, W1 in shared, shfl-broadcast cat
// ------------------------------------------------------------------
__global__ void k_gate(const int* __restrict__ rows, const int* __restrict__ cols,
                       const float* __restrict__ vals, const int* __restrict__ sidx,
                       const float* __restrict__ eps,
                       const float* __restrict__ W1, const float* __restrict__ b1,
                       const float* __restrict__ W2, const float* __restrict__ b2) {
    __shared__ float W1s[128 * 64];
    __shared__ float W2s[64];
    __shared__ float b1s[64];
    __shared__ float b2s;
    for (int i = threadIdx.x; i < 128 * 64; i += blockDim.x) W1s[i] = W1[i];
    if (threadIdx.x < 64) { W2s[threadIdx.x] = W2[threadIdx.x]; b1s[threadIdx.x] = b1[threadIdx.x]; }
    if (threadIdx.x == 0) b2s = b2[0];
    __syncthreads();

    const int lane = threadIdx.x & 31;
    const int warp_global = (blockIdx.x * blockDim.x + threadIdx.x) >> 5;
    const int nwarps = (gridDim.x * blockDim.x) >> 5;
    const float2* W1s2 = (const float2*)W1s;

    for (int s = warp_global; s < SS; s += nwarps) {
        int idx = sidx[s];
        int su = rows[idx];
        int sv = cols[idx];
        float cr[4];
        cr[0] = g_ego[su * DD + lane];
        cr[1] = g_ego[su * DD + 32 + lane];
        cr[2] = g_ego[sv * DD + lane];
        cr[3] = g_ego[sv * DD + 32 + lane];

        float accx = b1s[2 * lane];
        float accy = b1s[2 * lane + 1];
#pragma unroll
        for (int kk = 0; kk < 4; kk++) {
#pragma unroll
            for (int i = 0; i < 32; i++) {
                float ck = __shfl_sync(0xffffffffu, cr[kk], i);
                float2 w = W1s2[(kk * 32 + i) * 32 + lane];
                accx = fmaf(ck, w.x, accx);
                accy = fmaf(ck, w.y, accy);
            }
        }
        float h0 = fmaxf(accx, 0.f);
        float h1 = fmaxf(accy, 0.f);
        float part = h0 * W2s[2 * lane] + h1 * W2s[2 * lane + 1];
#pragma unroll
        for (int off = 16; off; off >>= 1)
            part += __shfl_xor_sync(0xffffffffu, part, off);
        if (lane == 0) {
            float logit = part + b2s;
            float e = eps[s] * (1.f - 2e-6f) + 1e-6f;
            float gumbel = logf(e) - log1pf(-e);
            float gate = 1.f / (1.f + expf(-(logit + gumbel) / TAU)) + EDGE_BIAS;
            atomicAdd(&g_gate_sum, (double)gate);
            if (g_lastS[idx] == s) g_masked[idx] = vals[idx] * gate;
        }
    }
}

// ------------------------------------------------------------------
// 5) CSR build
// ------------------------------------------------------------------
__global__ void k_count(const int* __restrict__ rows) {
    int e = blockIdx.x * blockDim.x + threadIdx.x;
    if (e >= EE) return;
    atomicAdd(&g_counts[rows[e]], 1);
}

__global__ void k_scan() {
    __shared__ int sh[1024];
    const int t = threadIdx.x;
    const int CH = (NTOT + 1023) / 1024;
    int start = t * CH;
    int end = start + CH; if (end > NTOT) end = NTOT;
    int s = 0;
    for (int i = start; i < end; i++) s += g_counts[i];
    sh[t] = s;
    __syncthreads();
    // Hillis-Steele inclusive scan
    for (int off = 1; off < 1024; off <<= 1) {
        int v = (t >= off) ? sh[t - off] : 0;
        __syncthreads();
        sh[t] += v;
        __syncthreads();
    }
    int run = sh[t] - s;  // exclusive base
    for (int i = start; i < end; i++) { g_rowptr[i] = run; run += g_counts[i]; }
    if (t == 1023) g_rowptr[NTOT] = sh[1023];
}

__global__ void k_fill(const int* __restrict__ rows, const int* __restrict__ cols,
                       const float* __restrict__ vals) {
    int e = blockIdx.x * blockDim.x + threadIdx.x;
    if (e >= EE) return;
    int r = rows[e];
    int slot = g_rowptr[r] + atomicAdd(&g_fillpos[r], 1);
    g_csr_col[slot] = cols[e];
    g_csr_val[slot] = vals[e];
    g_csr_mval[slot] = g_masked[e];
}

// ------------------------------------------------------------------
// 6) SPMM: warp per row, float2 per lane, accumulate into output sum
// ------------------------------------------------------------------
__global__ void k_spmm(const float* __restrict__ val,
                       const float* __restrict__ x_in,
                       float* __restrict__ x_out,
                       float* __restrict__ sum_out,
                       float scale) {
    int warp = (blockIdx.x * blockDim.x + threadIdx.x) >> 5;
    int lane = threadIdx.x & 31;
    if (warp >= NTOT) return;
    int s0 = g_rowptr[warp];
    int s1 = g_rowptr[warp + 1];
    const float2* x2 = (const float2*)x_in;
    float2 acc = make_float2(0.f, 0.f);
    for (int s = s0; s < s1; s++) {
        int c = __ldg(&g_csr_col[s]);
        float v = __ldg(&val[s]);
        float2 xv = x2[c * 32 + lane];
        acc.x = fmaf(v, xv.x, acc.x);
        acc.y = fmaf(v, xv.y, acc.y);
    }
    ((float2*)x_out)[warp * 32 + lane] = acc;
    float2* sp = (float2*)sum_out + warp * 32 + lane;
    float2 sv = *sp;
    sv.x = (sv.x + acc.x) * scale;
    sv.y = (sv.y + acc.y) * scale;
    *sp = sv;
}

// ------------------------------------------------------------------
// 7) gate mean
// ------------------------------------------------------------------
__global__ void k_final(float* __restrict__ out) {
    out[2 * NTOT * DD] = (float)(g_gate_sum / (double)SS);
}

extern "C" void kernel_launch(void* const* d_in, const int* in_sizes, int n_in,
                              void* d_out, int out_size) {
    const float* user = (const float*)d_in[0];
    const float* item = (const float*)d_in[1];
    const int*   rows = (const int*)d_in[2];
    const int*   cols = (const int*)d_in[3];
    const float* vals = (const float*)d_in[4];
    const int*   sidx = (const int*)d_in[5];
    const float* eps  = (const float*)d_in[6];
    const float* W1   = (const float*)d_in[7];
    const float* b1   = (const float*)d_in[8];
    const float* W2   = (const float*)d_in[9];
    const float* b2   = (const float*)d_in[10];
    float* out = (float*)d_out;

    float* ego; float* xa; float* xb; float* csr_val; float* csr_mval;
    cudaGetSymbolAddress((void**)&ego, g_ego);
    cudaGetSymbolAddress((void**)&xa, g_xa);
    cudaGetSymbolAddress((void**)&xb, g_xb);
    cudaGetSymbolAddress((void**)&csr_val, g_csr_val);
    cudaGetSymbolAddress((void**)&csr_mval, g_csr_mval);

    const int TB = 256;
    k_init_edges<<<(EE + TB - 1) / TB, TB>>>(vals);
    k_init_ego<<<(NTOT * DD + TB - 1) / TB, TB>>>(user, item, out);
    k_lastS<<<(SS + TB - 1) / TB, TB>>>(sidx);
    k_gate<<<1184, TB>>>(rows, cols, vals, sidx, eps, W1, b1, W2, b2);
    k_count<<<(EE + TB - 1) / TB, TB>>>(rows);
    k_scan<<<1, 1024>>>();
    k_fill<<<(EE + TB - 1) / TB, TB>>>(rows, cols, vals);

    const int SPMM_BLOCKS = (NTOT * 32 + TB - 1) / TB;
    float* sum0 = out;                 // orig chain sums
    float* sum1 = out + NTOT * DD;     // masked chain sums

    // original chain: ego -> xa -> xb -> xa
    k_spmm<<<SPMM_BLOCKS, TB>>>(csr_val, ego, xa, sum0, 1.0f);
    k_spmm<<<SPMM_BLOCKS, TB>>>(csr_val, xa, xb, sum0, 1.0f);
    k_spmm<<<SPMM_BLOCKS, TB>>>(csr_val, xb, xa, sum0, 0.25f);
    // masked chain: ego -> xb -> xa -> xb
    k_spmm<<<SPMM_BLOCKS, TB>>>(csr_mval, ego, xb, sum1, 1.0f);
    k_spmm<<<SPMM_BLOCKS, TB>>>(csr_mval, xb, xa, sum1, 1.0f);
    k_spmm<<<SPMM_BLOCKS, TB>>>(csr_mval, xa, xb, sum1, 0.25f);

    k_final<<<1, 1>>>(out);
}

// round 2
// speedup vs baseline: 1.6101x; 1.6101x over previous
#include <cuda_runtime.h>
#include <math.h>

#define NU 100000
#define NTOT 150000
#define DD 64
#define EE 1250000
#define SS 400000
#define TAU 0.2f
#define EDGE_BIAS 0.5f

// ---- static scratch (no allocations allowed) ----
__device__ float  g_ego[NTOT * DD];
__device__ float  g_xa[NTOT * DD];   // orig chain ping
__device__ float  g_xb[NTOT * DD];   // orig chain pong
__device__ float  g_xc[NTOT * DD];   // masked chain ping
__device__ float  g_xd[NTOT * DD];   // masked chain pong
__device__ float  g_masked[EE];
__device__ int    g_csr_col[EE];
__device__ float  g_csr_val[EE];
__device__ float  g_csr_mval[EE];
__device__ int    g_counts[NTOT];
__device__ int    g_fillpos[NTOT];
__device__ int    g_rowptr[NTOT + 1];
__device__ int    g_lastS[EE];
__device__ double g_gate_sum;

// ------------------------------------------------------------------
// 1) per-edge init
// ------------------------------------------------------------------
__global__ void k_init_edges(const float* __restrict__ vals) {
    int i = blockIdx.x * blockDim.x + threadIdx.x;
    if (i < EE) { g_masked[i] = vals[i]; g_lastS[i] = 0; }
    if (i < NTOT) { g_counts[i] = 0; g_fillpos[i] = 0; }
    if (i == 0) g_gate_sum = 0.0;
}

// ------------------------------------------------------------------
// 2) ego = concat(user, item); init both output sum regions
// ------------------------------------------------------------------
__global__ void k_init_ego(const float* __restrict__ user,
                           const float* __restrict__ item,
                           float* __restrict__ out) {
    int i = blockIdx.x * blockDim.x + threadIdx.x;
    if (i >= NTOT * DD) return;
    float v = (i < NU * DD) ? user[i] : item[i - NU * DD];
    g_ego[i] = v;
    out[i] = v;
    out[NTOT * DD + i] = v;
}

// ------------------------------------------------------------------
// 3) last-writer-wins marker for duplicate social_index entries
// ------------------------------------------------------------------
__global__ void k_lastS(const int* __restrict__ sidx) {
    int s = blockIdx.x * blockDim.x + threadIdx.x;
    if (s >= SS) return;
    atomicMax(&g_lastS[sidx[s]], s);
}

// ------------------------------------------------------------------
// 4) gate MLP as block GEMM with packed f32x2 FMA.
//    64 edges/block, 256 threads. C[64 edges][64 hidden], K=128.
//    Thread (tx,ty): tx=tid&15 -> 4 hidden cols, ty=tid>>4 -> 4 edge rows.
// ------------------------------------------------------------------
#define TE 64
#define CAT_STRIDE 132
#define GATE_SMEM ((TE * CAT_STRIDE + 128 * 64) * 4)

__global__ void __launch_bounds__(256, 2)
k_gate_gemm(const int* __restrict__ rows, const int* __restrict__ cols,
            const float* __restrict__ vals, const int* __restrict__ sidx,
            const float* __restrict__ eps,
            const float* __restrict__ W1, const float* __restrict__ b1,
            const float* __restrict__ W2, const float* __restrict__ b2) {
    extern __shared__ float sm[];
    float* catS = sm;                    // [64][132] row-major cat vectors
    float* Bs   = sm + TE * CAT_STRIDE;  // [128][64] = W1 as-is
    __shared__ float b1s[64], W2s[64];
    __shared__ int   eidx[TE];
    __shared__ double gpart[16];

    const int tid  = threadIdx.x;
    const int base = blockIdx.x * TE;

    for (int i = tid; i < 128 * 64; i += 256) Bs[i] = W1[i];
    if (tid < 64) { b1s[tid] = b1[tid]; W2s[tid] = W2[tid]; }

    // stage cat = [ego[su] | ego[sv]] for 64 edges (4 threads/edge)
    {
        int e = tid >> 2, p = tid & 3;
        int s = base + e;
        int idx = __ldg(&sidx[s]);
        if (p == 0) eidx[e] = idx;
        int node = (p < 2) ? __ldg(&rows[idx]) : __ldg(&cols[idx]);
        const float4* src = (const float4*)(g_ego + node * DD + (p & 1) * 32);
        float4* dst = (float4*)(catS + e * CAT_STRIDE + p * 32);
#pragma unroll
        for (int j = 0; j < 8; j++) dst[j] = src[j];
    }
    __syncthreads();

    const int tx = tid & 15, ty = tid >> 4;
    unsigned long long acc[4][2];
#pragma unroll
    for (int r = 0; r < 4; r++) { acc[r][0] = 0ull; acc[r][1] = 0ull; }

    const float* a0 = catS + (ty * 4 + 0) * CAT_STRIDE;
    const float* a1 = catS + (ty * 4 + 1) * CAT_STRIDE;
    const float* a2 = catS + (ty * 4 + 2) * CAT_STRIDE;
    const float* a3 = catS + (ty * 4 + 3) * CAT_STRIDE;
    const float* bcol = Bs + tx * 4;

#pragma unroll 4
    for (int k = 0; k < 128; k++) {
        unsigned long long B0 = *(const unsigned long long*)(bcol + k * 64);
        unsigned long long B1 = *(const unsigned long long*)(bcol + k * 64 + 2);
        float av[4];
        av[0] = a0[k]; av[1] = a1[k]; av[2] = a2[k]; av[3] = a3[k];
#pragma unroll
        for (int r = 0; r < 4; r++) {
            unsigned long long A2;
            unsigned int au = __float_as_uint(av[r]);
            asm("mov.b64 %0, {%1, %1};" : "=l"(A2) : "r"(au));
            asm("fma.rn.f32x2 %0, %1, %2, %0;" : "+l"(acc[r][0]) : "l"(A2), "l"(B0));
            asm("fma.rn.f32x2 %0, %1, %2, %0;" : "+l"(acc[r][1]) : "l"(A2), "l"(B1));
        }
    }

    // epilogue: logit = relu(C + b1) @ W2 + b2 per edge row
    float part[4] = {0.f, 0.f, 0.f, 0.f};
#pragma unroll
    for (int r = 0; r < 4; r++) {
#pragma unroll
        for (int cp = 0; cp < 2; cp++) {
            unsigned int lo_u, hi_u;
            asm("mov.b64 {%0, %1}, %2;" : "=r"(lo_u), "=r"(hi_u) : "l"(acc[r][cp]));
            int h0 = (tx << 2) + (cp << 1);
            float v0 = fmaxf(__uint_as_float(lo_u) + b1s[h0], 0.f);
            float v1 = fmaxf(__uint_as_float(hi_u) + b1s[h0 + 1], 0.f);
            part[r] = fmaf(v0, W2s[h0], part[r]);
            part[r] = fmaf(v1, W2s[h0 + 1], part[r]);
        }
    }
#pragma unroll
    for (int off = 8; off; off >>= 1) {
#pragma unroll
        for (int r = 0; r < 4; r++)
            part[r] += __shfl_xor_sync(0xffffffffu, part[r], off);
    }
    if (tx == 0) {
        float b2v = __ldg(b2);
        double lsum = 0.0;
#pragma unroll
        for (int r = 0; r < 4; r++) {
            int e = ty * 4 + r;
            int s = base + e;
            float logit = part[r] + b2v;
            float ee = eps[s] * (1.f - 2e-6f) + 1e-6f;
            float gumbel = logf(ee) - log1pf(-ee);
            float gate = 1.f / (1.f + expf(-(logit + gumbel) / TAU)) + EDGE_BIAS;
            lsum += (double)gate;
            int idx = eidx[e];
            if (g_lastS[idx] == s) g_masked[idx] = vals[idx] * gate;
        }
        gpart[ty] = lsum;
    }
    __syncthreads();
    if (tid == 0) {
        double t = 0.0;
#pragma unroll
        for (int i = 0; i < 16; i++) t += gpart[i];
        atomicAdd(&g_gate_sum, t);
    }
}

// ------------------------------------------------------------------
// 5) CSR build
// ------------------------------------------------------------------
__global__ void k_count(const int* __restrict__ rows) {
    int e = blockIdx.x * blockDim.x + threadIdx.x;
    if (e >= EE) return;
    atomicAdd(&g_counts[rows[e]], 1);
}

__global__ void k_scan() {
    __shared__ int sh[1024];
    const int t = threadIdx.x;
    const int CH = (NTOT + 1023) / 1024;
    int start = t * CH;
    int end = start + CH; if (end > NTOT) end = NTOT;
    int s = 0;
    for (int i = start; i < end; i++) s += g_counts[i];
    sh[t] = s;
    __syncthreads();
    for (int off = 1; off < 1024; off <<= 1) {
        int v = (t >= off) ? sh[t - off] : 0;
        __syncthreads();
        sh[t] += v;
        __syncthreads();
    }
    int run = sh[t] - s;
    for (int i = start; i < end; i++) { g_rowptr[i] = run; run += g_counts[i]; }
    if (t == 1023) g_rowptr[NTOT] = sh[1023];
}

__global__ void k_fill(const int* __restrict__ rows, const int* __restrict__ cols,
                       const float* __restrict__ vals) {
    int e = blockIdx.x * blockDim.x + threadIdx.x;
    if (e >= EE) return;
    int r = rows[e];
    int slot = g_rowptr[r] + atomicAdd(&g_fillpos[r], 1);
    g_csr_col[slot] = cols[e];
    g_csr_val[slot] = vals[e];
    g_csr_mval[slot] = g_masked[e];
}

// ------------------------------------------------------------------
// 6) fused SPMM layer 1: both chains gather ego once
// ------------------------------------------------------------------
__global__ void k_spmm_l1(const float* __restrict__ va, const float* __restrict__ vb,
                          const float* __restrict__ x_in,
                          float* __restrict__ xa_out, float* __restrict__ xb_out,
                          float* __restrict__ out) {
    int warp = (blockIdx.x * blockDim.x + threadIdx.x) >> 5;
    int lane = threadIdx.x & 31;
    if (warp >= NTOT) return;
    int s0 = __ldg(&g_rowptr[warp]);
    int s1 = __ldg(&g_rowptr[warp + 1]);
    const float2* X = (const float2*)x_in;
    float2 aa = make_float2(0.f, 0.f), ab = make_float2(0.f, 0.f);
    for (int s = s0; s < s1; s++) {
        int c = __ldg(&g_csr_col[s]);
        float v1 = __ldg(&va[s]);
        float v2 = __ldg(&vb[s]);
        float2 xv = __ldg(&X[c * 32 + lane]);
        aa.x = fmaf(v1, xv.x, aa.x); aa.y = fmaf(v1, xv.y, aa.y);
        ab.x = fmaf(v2, xv.x, ab.x); ab.y = fmaf(v2, xv.y, ab.y);
    }
    int o = warp * 32 + lane;
    ((float2*)xa_out)[o] = aa;
    ((float2*)xb_out)[o] = ab;
    float2* s0p = (float2*)out + o;
    float2* s1p = (float2*)out + NTOT * 32 + o;
    float2 u = *s0p; u.x += aa.x; u.y += aa.y; *s0p = u;
    float2 w = *s1p; w.x += ab.x; w.y += ab.y; *s1p = w;
}

// ------------------------------------------------------------------
// 7) fused SPMM layers 2/3: two gathers per edge
// ------------------------------------------------------------------
__global__ void k_spmm_dual(const float* __restrict__ va, const float* __restrict__ vb,
                            const float* __restrict__ xa_in, const float* __restrict__ xb_in,
                            float* __restrict__ xa_out, float* __restrict__ xb_out,
                            float* __restrict__ out, float scale) {
    int warp = (blockIdx.x * blockDim.x + threadIdx.x) >> 5;
    int lane = threadIdx.x & 31;
    if (warp >= NTOT) return;
    int s0 = __ldg(&g_rowptr[warp]);
    int s1 = __ldg(&g_rowptr[warp + 1]);
    const float2* XA = (const float2*)xa_in;
    const float2* XB = (const float2*)xb_in;
    float2 aa = make_float2(0.f, 0.f), ab = make_float2(0.f, 0.f);
    for (int s = s0; s < s1; s++) {
        int c = __ldg(&g_csr_col[s]);
        float v1 = __ldg(&va[s]);
        float v2 = __ldg(&vb[s]);
        float2 x1 = __ldg(&XA[c * 32 + lane]);
        float2 x2 = __ldg(&XB[c * 32 + lane]);
        aa.x = fmaf(v1, x1.x, aa.x); aa.y = fmaf(v1, x1.y, aa.y);
        ab.x = fmaf(v2, x2.x, ab.x); ab.y = fmaf(v2, x2.y, ab.y);
    }
    int o = warp * 32 + lane;
    ((float2*)xa_out)[o] = aa;
    ((float2*)xb_out)[o] = ab;
    float2* s0p = (float2*)out + o;
    float2* s1p = (float2*)out + NTOT * 32 + o;
    float2 u = *s0p; u.x = (u.x + aa.x) * scale; u.y = (u.y + aa.y) * scale; *s0p = u;
    float2 w = *s1p; w.x = (w.x + ab.x) * scale; w.y = (w.y + ab.y) * scale; *s1p = w;
}

// ------------------------------------------------------------------
// 8) gate mean
// ------------------------------------------------------------------
__global__ void k_final(float* __restrict__ out) {
    out[2 * NTOT * DD] = (float)(g_gate_sum / (double)SS);
}

extern "C" void kernel_launch(void* const* d_in, const int* in_sizes, int n_in,
                              void* d_out, int out_size) {
    const float* user = (const float*)d_in[0];
    const float* item = (const float*)d_in[1];
    const int*   rows = (const int*)d_in[2];
    const int*   cols = (const int*)d_in[3];
    const float* vals = (const float*)d_in[4];
    const int*   sidx = (const int*)d_in[5];
    const float* eps  = (const float*)d_in[6];
    const float* W1   = (const float*)d_in[7];
    const float* b1   = (const float*)d_in[8];
    const float* W2   = (const float*)d_in[9];
    const float* b2   = (const float*)d_in[10];
    float* out = (float*)d_out;

    float* ego; float* xa; float* xb; float* xc; float* xd;
    float* csr_val; float* csr_mval;
    cudaGetSymbolAddress((void**)&ego, g_ego);
    cudaGetSymbolAddress((void**)&xa, g_xa);
    cudaGetSymbolAddress((void**)&xb, g_xb);
    cudaGetSymbolAddress((void**)&xc, g_xc);
    cudaGetSymbolAddress((void**)&xd, g_xd);
    cudaGetSymbolAddress((void**)&csr_val, g_csr_val);
    cudaGetSymbolAddress((void**)&csr_mval, g_csr_mval);

    static int smem_set = 0;
    if (!smem_set) {
        cudaFuncSetAttribute(k_gate_gemm,
                             cudaFuncAttributeMaxDynamicSharedMemorySize, GATE_SMEM);
        smem_set = 1;
    }

    const int TB = 256;
    k_init_edges<<<(EE + TB - 1) / TB, TB>>>(vals);
    k_init_ego<<<(NTOT * DD + TB - 1) / TB, TB>>>(user, item, out);
    k_lastS<<<(SS + TB - 1) / TB, TB>>>(sidx);
    k_count<<<(EE + TB - 1) / TB, TB>>>(rows);
    k_scan<<<1, 1024>>>();
    k_gate_gemm<<<SS / TE, 256, GATE_SMEM>>>(rows, cols, vals, sidx, eps, W1, b1, W2, b2);
    k_fill<<<(EE + TB - 1) / TB, TB>>>(rows, cols, vals);

    const int SPMM_BLOCKS = (NTOT * 32 + TB - 1) / TB;
    k_spmm_l1  <<<SPMM_BLOCKS, TB>>>(csr_val, csr_mval, ego, xa, xc, out);
    k_spmm_dual<<<SPMM_BLOCKS, TB>>>(csr_val, csr_mval, xa, xc, xb, xd, out, 1.0f);
    k_spmm_dual<<<SPMM_BLOCKS, TB>>>(csr_val, csr_mval, xb, xd, xa, xc, out, 0.25f);

    k_final<<<1, 1>>>(out);
}

// round 3
// speedup vs baseline: 2.3237x; 1.4432x over previous
#include <cuda_runtime.h>
#include <math.h>

#define NU 100000
#define NTOT 150000
#define DD 64
#define EE 1250000
#define SS 400000
#define TAU 0.2f
#define EDGE_BIAS 0.5f
#define SCAN_B 586   // ceil(NTOT/256)

// ---- static scratch (no allocations allowed) ----
__device__ float  g_ego[NTOT * DD];        // 38.4 MB
__device__ float  g_l1[NTOT * 2 * DD];     // 76.8 MB  [row][0:64]=orig, [64:128]=masked
__device__ float  g_l2[NTOT * 2 * DD];     // 76.8 MB
__device__ float  g_masked[EE];
__device__ int    g_csr_col[EE];
__device__ float2 g_csr_vals2[EE];         // {val, masked_val}
__device__ int    g_counts[NTOT];
__device__ int    g_fillpos[NTOT];
__device__ int    g_rowptr[NTOT + 1];
__device__ int    g_bsum[1024];
__device__ int    g_lastS[EE];
__device__ double g_gate_sum;

// ------------------------------------------------------------------
// 1) per-edge init
// ------------------------------------------------------------------
__global__ void k_init_edges(const float* __restrict__ vals) {
    int i = blockIdx.x * blockDim.x + threadIdx.x;
    if (i < EE) { g_masked[i] = vals[i]; g_lastS[i] = 0; }
    if (i < NTOT) { g_counts[i] = 0; g_fillpos[i] = 0; }
    if (i == 0) g_gate_sum = 0.0;
}

// ------------------------------------------------------------------
// 2) ego = concat(user, item)
// ------------------------------------------------------------------
__global__ void k_init_ego(const float* __restrict__ user,
                           const float* __restrict__ item) {
    int i = blockIdx.x * blockDim.x + threadIdx.x;
    if (i >= NTOT * DD) return;
    g_ego[i] = (i < NU * DD) ? user[i] : item[i - NU * DD];
}

// ------------------------------------------------------------------
// 3) last-writer-wins marker for duplicate social_index entries
// ------------------------------------------------------------------
__global__ void k_lastS(const int* __restrict__ sidx) {
    int s = blockIdx.x * blockDim.x + threadIdx.x;
    if (s >= SS) return;
    atomicMax(&g_lastS[sidx[s]], s);
}

// ------------------------------------------------------------------
// 4) gate MLP as block GEMM with packed f32x2 FMA.
//    128 edges/block, 256 threads. C[128 edges][64 hidden], K=128.
//    tx=tid&15 -> 4 hidden cols, ty=tid>>4 -> 8 edge rows.
// ------------------------------------------------------------------
#define TE 128
#define CAT_STRIDE 132
#define GATE_SMEM ((TE * CAT_STRIDE + 128 * 64) * 4)

__global__ void __launch_bounds__(256, 2)
k_gate_gemm(const int* __restrict__ rows, const int* __restrict__ cols,
            const float* __restrict__ vals, const int* __restrict__ sidx,
            const float* __restrict__ eps,
            const float* __restrict__ W1, const float* __restrict__ b1,
            const float* __restrict__ W2, const float* __restrict__ b2) {
    extern __shared__ float sm[];
    float* catS = sm;                    // [128 edges][132]
    float* Bs   = sm + TE * CAT_STRIDE;  // [128 k][64 hidden]
    __shared__ float b1s[64], W2s[64];
    __shared__ int   eidx[TE];
    __shared__ double gpart[16];

    const int tid  = threadIdx.x;
    const int base = blockIdx.x * TE;

    for (int i = tid; i < 128 * 64; i += 256) Bs[i] = W1[i];
    if (tid < 64) { b1s[tid] = b1[tid]; W2s[tid] = W2[tid]; }

    // stage cat = [ego[su] | ego[sv]] : 2 threads per edge
    {
        int e = tid >> 1, p = tid & 1;
        int s = base + e;
        int idx = __ldg(&sidx[s]);
        if (p == 0) eidx[e] = idx;
        int node = p ? __ldg(&cols[idx]) : __ldg(&rows[idx]);
        const float4* src = (const float4*)(g_ego + node * DD);
        float4* dst = (float4*)(catS + e * CAT_STRIDE + p * DD);
#pragma unroll
        for (int j = 0; j < 16; j++) dst[j] = src[j];
    }
    __syncthreads();

    const int tx = tid & 15, ty = tid >> 4;
    unsigned long long acc[8][2];
#pragma unroll
    for (int r = 0; r < 8; r++) { acc[r][0] = 0ull; acc[r][1] = 0ull; }

    const float* abase = catS + ty * 8 * CAT_STRIDE;
    const float* bcol  = Bs + tx * 4;

#pragma unroll 4
    for (int k = 0; k < 128; k++) {
        unsigned long long B0 = *(const unsigned long long*)(bcol + k * 64);
        unsigned long long B1 = *(const unsigned long long*)(bcol + k * 64 + 2);
#pragma unroll
        for (int r = 0; r < 8; r++) {
            unsigned int au = __float_as_uint(abase[r * CAT_STRIDE + k]);
            unsigned long long A2;
            asm("mov.b64 %0, {%1, %1};" : "=l"(A2) : "r"(au));
            asm("fma.rn.f32x2 %0, %1, %2, %0;" : "+l"(acc[r][0]) : "l"(A2), "l"(B0));
            asm("fma.rn.f32x2 %0, %1, %2, %0;" : "+l"(acc[r][1]) : "l"(A2), "l"(B1));
        }
    }

    // epilogue: per edge logit = relu(C + b1) @ W2 + b2
    float part[8];
#pragma unroll
    for (int r = 0; r < 8; r++) {
        float p = 0.f;
#pragma unroll
        for (int cp = 0; cp < 2; cp++) {
            unsigned int lo_u, hi_u;
            asm("mov.b64 {%0, %1}, %2;" : "=r"(lo_u), "=r"(hi_u) : "l"(acc[r][cp]));
            int h0 = (tx << 2) + (cp << 1);
            float v0 = fmaxf(__uint_as_float(lo_u) + b1s[h0], 0.f);
            float v1 = fmaxf(__uint_as_float(hi_u) + b1s[h0 + 1], 0.f);
            p = fmaf(v0, W2s[h0], p);
            p = fmaf(v1, W2s[h0 + 1], p);
        }
        part[r] = p;
    }
#pragma unroll
    for (int off = 8; off; off >>= 1)
#pragma unroll
        for (int r = 0; r < 8; r++)
            part[r] += __shfl_xor_sync(0xffffffffu, part[r], off);

    if (tx == 0) {
        float b2v = __ldg(b2);
        double lsum = 0.0;
#pragma unroll
        for (int r = 0; r < 8; r++) {
            int e = ty * 8 + r;
            int s = base + e;
            float logit = part[r] + b2v;
            float ee = eps[s] * (1.f - 2e-6f) + 1e-6f;
            float gumbel = logf(ee) - log1pf(-ee);
            float gate = 1.f / (1.f + expf(-(logit + gumbel) / TAU)) + EDGE_BIAS;
            lsum += (double)gate;
            int idx = eidx[e];
            if (g_lastS[idx] == s) g_masked[idx] = vals[idx] * gate;
        }
        gpart[ty] = lsum;
    }
    __syncthreads();
    if (tid == 0) {
        double t = 0.0;
#pragma unroll
        for (int i = 0; i < 16; i++) t += gpart[i];
        atomicAdd(&g_gate_sum, t);
    }
}

// ------------------------------------------------------------------
// 5) CSR build: count + 3-phase scan + fill
// ------------------------------------------------------------------
__global__ void k_count(const int* __restrict__ rows) {
    int e = blockIdx.x * blockDim.x + threadIdx.x;
    if (e >= EE) return;
    atomicAdd(&g_counts[rows[e]], 1);
}

__global__ void k_scan1() {
    __shared__ int sh[256];
    int i = blockIdx.x * 256 + threadIdx.x;
    int v = (i < NTOT) ? g_counts[i] : 0;
    sh[threadIdx.x] = v;
    __syncthreads();
    for (int off = 128; off; off >>= 1) {
        if (threadIdx.x < off) sh[threadIdx.x] += sh[threadIdx.x + off];
        __syncthreads();
    }
    if (threadIdx.x == 0) g_bsum[blockIdx.x] = sh[0];
}

__global__ void k_scan2() {
    __shared__ int sh[1024];
    int t = threadIdx.x;
    int v = (t < SCAN_B) ? g_bsum[t] : 0;
    sh[t] = v;
    __syncthreads();
    for (int off = 1; off < 1024; off <<= 1) {
        int u = (t >= off) ? sh[t - off] : 0;
        __syncthreads();
        sh[t] += u;
        __syncthreads();
    }
    if (t < SCAN_B) g_bsum[t] = sh[t] - v;  // exclusive
}

__global__ void k_scan3() {
    __shared__ int sh[256];
    int i = blockIdx.x * 256 + threadIdx.x;
    int v = (i < NTOT) ? g_counts[i] : 0;
    sh[threadIdx.x] = v;
    __syncthreads();
    for (int off = 1; off < 256; off <<= 1) {
        int u = (threadIdx.x >= off) ? sh[threadIdx.x - off] : 0;
        __syncthreads();
        sh[threadIdx.x] += u;
        __syncthreads();
    }
    if (i < NTOT) g_rowptr[i] = g_bsum[blockIdx.x] + sh[threadIdx.x] - v;
    if (i == 0) g_rowptr[NTOT] = EE;
}

__global__ void k_fill(const int* __restrict__ rows, const int* __restrict__ cols,
                       const float* __restrict__ vals) {
    int e = blockIdx.x * blockDim.x + threadIdx.x;
    if (e >= EE) return;
    int r = rows[e];
    int slot = g_rowptr[r] + atomicAdd(&g_fillpos[r], 1);
    g_csr_col[slot] = cols[e];
    g_csr_vals2[slot] = make_float2(vals[e], g_masked[e]);
}

// ------------------------------------------------------------------
// 6) SPMM layer 1: both chains gather ego once -> interleaved l1
// ------------------------------------------------------------------
__device__ __forceinline__ void fma2(float2& a, float v, float2 x) {
    a.x = fmaf(v, x.x, a.x); a.y = fmaf(v, x.y, a.y);
}

__global__ void k_spmm_l1() {
    int warp = (blockIdx.x * blockDim.x + threadIdx.x) >> 5;
    int lane = threadIdx.x & 31;
    if (warp >= NTOT) return;
    int s0 = __ldg(&g_rowptr[warp]);
    int s1 = __ldg(&g_rowptr[warp + 1]);
    const float2* X = (const float2*)g_ego;
    float2 aa = make_float2(0.f, 0.f), ab = make_float2(0.f, 0.f);
    int s = s0;
    for (; s + 4 <= s1; s += 4) {
        int c0 = __ldg(&g_csr_col[s]),     c1 = __ldg(&g_csr_col[s + 1]);
        int c2 = __ldg(&g_csr_col[s + 2]), c3 = __ldg(&g_csr_col[s + 3]);
        float2 v0 = __ldg(&g_csr_vals2[s]),     v1 = __ldg(&g_csr_vals2[s + 1]);
        float2 v2 = __ldg(&g_csr_vals2[s + 2]), v3 = __ldg(&g_csr_vals2[s + 3]);
        float2 x0 = __ldg(&X[c0 * 32 + lane]);
        float2 x1 = __ldg(&X[c1 * 32 + lane]);
        float2 x2 = __ldg(&X[c2 * 32 + lane]);
        float2 x3 = __ldg(&X[c3 * 32 + lane]);
        fma2(aa, v0.x, x0); fma2(ab, v0.y, x0);
        fma2(aa, v1.x, x1); fma2(ab, v1.y, x1);
        fma2(aa, v2.x, x2); fma2(ab, v2.y, x2);
        fma2(aa, v3.x, x3); fma2(ab, v3.y, x3);
    }
    for (; s < s1; s++) {
        int c = __ldg(&g_csr_col[s]);
        float2 v = __ldg(&g_csr_vals2[s]);
        float2 x = __ldg(&X[c * 32 + lane]);
        fma2(aa, v.x, x); fma2(ab, v.y, x);
    }
    float2* L1 = (float2*)g_l1;
    L1[warp * 64 + lane] = aa;
    L1[warp * 64 + 32 + lane] = ab;
}

// ------------------------------------------------------------------
// 7) SPMM layer 2: interleaved l1 -> interleaved l2
// ------------------------------------------------------------------
__global__ void k_spmm_l2() {
    int warp = (blockIdx.x * blockDim.x + threadIdx.x) >> 5;
    int lane = threadIdx.x & 31;
    if (warp >= NTOT) return;
    int s0 = __ldg(&g_rowptr[warp]);
    int s1 = __ldg(&g_rowptr[warp + 1]);
    const float2* X = (const float2*)g_l1;
    float2 aa = make_float2(0.f, 0.f), ab = make_float2(0.f, 0.f);
    int s = s0;
    for (; s + 2 <= s1; s += 2) {
        int c0 = __ldg(&g_csr_col[s]), c1 = __ldg(&g_csr_col[s + 1]);
        float2 v0 = __ldg(&g_csr_vals2[s]), v1 = __ldg(&g_csr_vals2[s + 1]);
        float2 xa0 = __ldg(&X[c0 * 64 + lane]);
        float2 xb0 = __ldg(&X[c0 * 64 + 32 + lane]);
        float2 xa1 = __ldg(&X[c1 * 64 + lane]);
        float2 xb1 = __ldg(&X[c1 * 64 + 32 + lane]);
        fma2(aa, v0.x, xa0); fma2(ab, v0.y, xb0);
        fma2(aa, v1.x, xa1); fma2(ab, v1.y, xb1);
    }
    for (; s < s1; s++) {
        int c = __ldg(&g_csr_col[s]);
        float2 v = __ldg(&g_csr_vals2[s]);
        float2 xa = __ldg(&X[c * 64 + lane]);
        float2 xb = __ldg(&X[c * 64 + 32 + lane]);
        fma2(aa, v.x, xa); fma2(ab, v.y, xb);
    }
    float2* L2 = (float2*)g_l2;
    L2[warp * 64 + lane] = aa;
    L2[warp * 64 + 32 + lane] = ab;
}

// ------------------------------------------------------------------
// 8) SPMM layer 3 fused with mean: out = (ego + l1 + l2 + l3) / 4
// ------------------------------------------------------------------
__global__ void k_spmm_l3(float* __restrict__ out) {
    int warp = (blockIdx.x * blockDim.x + threadIdx.x) >> 5;
    int lane = threadIdx.x & 31;
    if (warp >= NTOT) return;
    int s0 = __ldg(&g_rowptr[warp]);
    int s1 = __ldg(&g_rowptr[warp + 1]);
    const float2* X = (const float2*)g_l2;
    float2 aa = make_float2(0.f, 0.f), ab = make_float2(0.f, 0.f);
    int s = s0;
    for (; s + 2 <= s1; s += 2) {
        int c0 = __ldg(&g_csr_col[s]), c1 = __ldg(&g_csr_col[s + 1]);
        float2 v0 = __ldg(&g_csr_vals2[s]), v1 = __ldg(&g_csr_vals2[s + 1]);
        float2 xa0 = __ldg(&X[c0 * 64 + lane]);
        float2 xb0 = __ldg(&X[c0 * 64 + 32 + lane]);
        float2 xa1 = __ldg(&X[c1 * 64 + lane]);
        float2 xb1 = __ldg(&X[c1 * 64 + 32 + lane]);
        fma2(aa, v0.x, xa0); fma2(ab, v0.y, xb0);
        fma2(aa, v1.x, xa1); fma2(ab, v1.y, xb1);
    }
    for (; s < s1; s++) {
        int c = __ldg(&g_csr_col[s]);
        float2 v = __ldg(&g_csr_vals2[s]);
        float2 xa = __ldg(&X[c * 64 + lane]);
        float2 xb = __ldg(&X[c * 64 + 32 + lane]);
        fma2(aa, v.x, xa); fma2(ab, v.y, xb);
    }
    const float2* E  = (const float2*)g_ego;
    const float2* L1 = (const float2*)g_l1;
    const float2* L2 = (const float2*)g_l2;
    float2 e  = E[warp * 32 + lane];
    float2 p1 = L1[warp * 64 + lane];
    float2 q1 = L1[warp * 64 + 32 + lane];
    float2 p2 = L2[warp * 64 + lane];
    float2 q2 = L2[warp * 64 + 32 + lane];
    float2* outA = (float2*)out;
    float2* outB = (float2*)out + NTOT * 32;
    outA[warp * 32 + lane] = make_float2((e.x + p1.x + p2.x + aa.x) * 0.25f,
                                         (e.y + p1.y + p2.y + aa.y) * 0.25f);
    outB[warp * 32 + lane] = make_float2((e.x + q1.x + q2.x + ab.x) * 0.25f,
                                         (e.y + q1.y + q2.y + ab.y) * 0.25f);
}

// ------------------------------------------------------------------
// 9) gate mean
// ------------------------------------------------------------------
__global__ void k_final(float* __restrict__ out) {
    out[2 * NTOT * DD] = (float)(g_gate_sum / (double)SS);
}

extern "C" void kernel_launch(void* const* d_in, const int* in_sizes, int n_in,
                              void* d_out, int out_size) {
    const float* user = (const float*)d_in[0];
    const float* item = (const float*)d_in[1];
    const int*   rows = (const int*)d_in[2];
    const int*   cols = (const int*)d_in[3];
    const float* vals = (const float*)d_in[4];
    const int*   sidx = (const int*)d_in[5];
    const float* eps  = (const float*)d_in[6];
    const float* W1   = (const float*)d_in[7];
    const float* b1   = (const float*)d_in[8];
    const float* W2   = (const float*)d_in[9];
    const float* b2   = (const float*)d_in[10];
    float* out = (float*)d_out;

    static int smem_set = 0;
    if (!smem_set) {
        cudaFuncSetAttribute(k_gate_gemm,
                             cudaFuncAttributeMaxDynamicSharedMemorySize, GATE_SMEM);
        smem_set = 1;
    }

    const int TB = 256;
    k_init_edges<<<(EE + TB - 1) / TB, TB>>>(vals);
    k_init_ego<<<(NTOT * DD + TB - 1) / TB, TB>>>(user, item);
    k_lastS<<<(SS + TB - 1) / TB, TB>>>(sidx);
    k_gate_gemm<<<SS / TE, 256, GATE_SMEM>>>(rows, cols, vals, sidx, eps, W1, b1, W2, b2);
    k_count<<<(EE + TB - 1) / TB, TB>>>(rows);
    k_scan1<<<SCAN_B, 256>>>();
    k_scan2<<<1, 1024>>>();
    k_scan3<<<SCAN_B, 256>>>();
    k_fill<<<(EE + TB - 1) / TB, TB>>>(rows, cols, vals);

    const int SPMM_BLOCKS = (NTOT * 32 + TB - 1) / TB;
    k_spmm_l1<<<SPMM_BLOCKS, TB>>>();
    k_spmm_l2<<<SPMM_BLOCKS, TB>>>();
    k_spmm_l3<<<SPMM_BLOCKS, TB>>>(out);

    k_final<<<1, 1>>>(out);
}